// round 11
// baseline (speedup 1.0000x reference)
#include <cuda.h>
#include <cuda_runtime.h>
#include <cstdint>

// Problem constants
#define B_DIM 128
#define L_DIM 1024
#define D_DIM 128
#define DVF   32          // D/4 float4 groups (full row)
#define DT    8           // float4 groups per D-tile (D split 4 ways)
#define TS    64          // output start positions per L tile
#define NPOS  96          // TS + 31 halo, padded to 96
#define NS4   92          // TS + 28 sliding-4-sum rows
#define NTHREADS 512

// Output row offsets for window sizes 4, 8, 16, 32
#define OFF4  0
#define OFF8  1021
#define OFF16 2038
#define OFF32 3047
#define ROWS  4040

// Shared memory (floats):
//   s4     : NS4*DT float4      = 11776 B
//   ostage : 4*TS*DT float4     = 32768 B
//   inv    : 4*TS floats        = 1024 B
//   msk    : NPOS ints          = 384 B
#define S4_F4  (NS4 * DT)
#define OST_F4 (4 * TS * DT)
#define SMEM_FLOATS (S4_F4 * 4 + OST_F4 * 4 + 4 * TS + NPOS)
#define SMEM_BYTES  (SMEM_FLOATS * 4)

__device__ __forceinline__ float4 add4(float4 a, float4 b) {
    return make_float4(a.x + b.x, a.y + b.y, a.z + b.z, a.w + b.w);
}
__device__ __forceinline__ float4 scl4(float4 a, float s) {
    return make_float4(a.x * s, a.y * s, a.z * s, a.w * s);
}
__device__ __forceinline__ uint32_t smem_u32(const void* p) {
    return (uint32_t)__cvta_generic_to_shared(p);
}

extern __shared__ float smem_raw[];

__global__ __launch_bounds__(NTHREADS, 4)
void msse_kernel(const float* __restrict__ x,
                 const int* __restrict__ mask,
                 float* __restrict__ out,
                 const __grid_constant__ CUtensorMap tmap,
                 const int use_tma)
{
    const int s0    = blockIdx.x * TS;        // global start of this L tile
    const int dbase = blockIdx.y * DT;        // float4-group base of D tile
    const int b     = blockIdx.z;
    const int tid   = threadIdx.x;

    float4* s4  = reinterpret_cast<float4*>(smem_raw);          // NS4*DT f4
    float4* ost = s4 + S4_F4;                                   // 4*TS*DT f4
    float*  inv = reinterpret_cast<float*>(ost + OST_F4);       // 4*TS
    int*    msk = reinterpret_cast<int*>(inv + 4 * TS);         // NPOS

    // ---- phase 1: mask tile (with halo), zero-pad past L ----
    const int* mrow = mask + (size_t)b * L_DIM;
    if (tid < NPOS) {
        int g = s0 + tid;
        msk[tid] = (g < L_DIM) ? mrow[g] : 0;
    }
    __syncthreads();

    const float4* xrow = reinterpret_cast<const float4*>(x + (size_t)b * L_DIM * D_DIM);
    const float4 fz = make_float4(0.f, 0.f, 0.f, 0.f);

    // ---- phase 2a: build s4 from global (predicated loads; L2 absorbs reuse) ----
    for (int i = tid; i < NS4 * DT; i += NTHREADS) {
        int p = i >> 3;
        int q = i & 7;
        const float4* base = xrow + (size_t)(s0 + p) * DVF + dbase + q;
        float4 acc = fz;
        #pragma unroll
        for (int k = 0; k < 4; k++) {
            if (msk[p + k]) acc = add4(acc, __ldg(base + k * DVF));
        }
        s4[i] = acc;
    }

    // ---- phase 2b: per-start window-length reciprocals ----
    if (tid < TS) {
        int j = tid;
        int c = 0;
        #pragma unroll
        for (int k = 0; k < 4; k++)  c += msk[j + k];
        int c4 = c;
        #pragma unroll
        for (int k = 4; k < 8; k++)  c += msk[j + k];
        int c8 = c;
        #pragma unroll
        for (int k = 8; k < 16; k++) c += msk[j + k];
        int c16 = c;
        #pragma unroll
        for (int k = 16; k < 32; k++) c += msk[j + k];
        int c32 = c;
        inv[0 * TS + j] = 1.0f / (float)(c4  > 1 ? c4  : 1);
        inv[1 * TS + j] = 1.0f / (float)(c8  > 1 ? c8  : 1);
        inv[2 * TS + j] = 1.0f / (float)(c16 > 1 ? c16 : 1);
        inv[3 * TS + j] = 1.0f / (float)(c32 > 1 ? c32 : 1);
    }
    __syncthreads();

    // Tile fully valid for ALL windows iff last start s0+63 <= 1024-32
    const bool full = use_tma && (s0 + TS - 1 <= L_DIM - 32);

    // ---- phase 3: one start per thread (8 LDS.128, sequential consumption) ----
    {
        const int q  = tid & 7;
        const int j  = tid >> 3;        // 0..63
        const int gi = s0 + j;
        const float4* sp = s4 + j * DT + q;

        const float i4  = inv[0 * TS + j];
        const float i8  = inv[1 * TS + j];
        const float i16 = inv[2 * TS + j];
        const float i32 = inv[3 * TS + j];

        float4 acc = sp[0];
        float4 o4  = scl4(acc, i4);
        acc = add4(acc, sp[4 * DT]);
        float4 o8  = scl4(acc, i8);
        acc = add4(acc, add4(sp[8 * DT], sp[12 * DT]));
        float4 o16 = scl4(acc, i16);
        acc = add4(acc, add4(add4(sp[16 * DT], sp[20 * DT]),
                             add4(sp[24 * DT], sp[28 * DT])));
        float4 o32 = scl4(acc, i32);

        if (full) {
            // stage into smem (STS.128) for TMA bulk store
            ost[(0 * TS + j) * DT + q] = o4;
            ost[(1 * TS + j) * DT + q] = o8;
            ost[(2 * TS + j) * DT + q] = o16;
            ost[(3 * TS + j) * DT + q] = o32;
        } else {
            // tail tile (or fallback): direct streaming stores with bounds
            float4* outb = reinterpret_cast<float4*>(out + (size_t)b * ROWS * D_DIM);
            const int oq = dbase + q;
            if (gi <= L_DIM - 4)
                __stcs(&outb[(OFF4  + gi) * DVF + oq], o4);
            if (gi <= L_DIM - 8)
                __stcs(&outb[(OFF8  + gi) * DVF + oq], o8);
            if (gi <= L_DIM - 16)
                __stcs(&outb[(OFF16 + gi) * DVF + oq], o16);
            if (gi <= L_DIM - 32)
                __stcs(&outb[(OFF32 + gi) * DVF + oq], o32);
        }
    }

    if (full) {
        __syncthreads();   // ostage complete
        if (tid == 0) {
            asm volatile("fence.proxy.async.shared::cta;" ::: "memory");
            const uint32_t sb = smem_u32(ost);
            const int c0 = dbase * 4;                 // element coord in D
            const int r  = b * ROWS + s0;
            #define TMA_ST(woff, widx) \
                asm volatile( \
                    "cp.async.bulk.tensor.2d.global.shared::cta.tile.bulk_group " \
                    "[%0, {%1, %2}], [%3];" \
                    :: "l"(&tmap), "r"(c0), "r"(r + (woff)), \
                       "r"(sb + (widx) * TS * DT * 16) : "memory")
            TMA_ST(OFF4,  0);
            TMA_ST(OFF8,  1);
            TMA_ST(OFF16, 2);
            TMA_ST(OFF32, 3);
            #undef TMA_ST
            asm volatile("cp.async.bulk.commit_group;" ::: "memory");
            asm volatile("cp.async.bulk.wait_group 0;" ::: "memory");
        }
    }
}

// ---- host side ----

typedef CUresult (CUDAAPI *PFN_encodeTiled_t)(
    CUtensorMap*, CUtensorMapDataType, cuuint32_t, void*,
    const cuuint64_t*, const cuuint64_t*, const cuuint32_t*, const cuuint32_t*,
    CUtensorMapInterleave, CUtensorMapSwizzle, CUtensorMapL2promotion,
    CUtensorMapFloatOOBfill);

extern "C" void kernel_launch(void* const* d_in, const int* in_sizes, int n_in,
                              void* d_out, int out_size)
{
    const float* x    = (const float*)d_in[0];
    const int*   mask = (const int*)d_in[1];
    float*       out  = (float*)d_out;

    cudaFuncSetAttribute(msse_kernel,
                         cudaFuncAttributeMaxDynamicSharedMemorySize, SMEM_BYTES);

    // Acquire cuTensorMapEncodeTiled through the runtime (no -lcuda needed).
    CUtensorMap tmap;
    memset(&tmap, 0, sizeof(tmap));
    int use_tma = 0;

    void* fp = nullptr;
    cudaDriverEntryPointQueryResult qr;
    if (cudaGetDriverEntryPoint("cuTensorMapEncodeTiled", &fp,
                                cudaEnableDefault, &qr) == cudaSuccess && fp) {
        PFN_encodeTiled_t encode = (PFN_encodeTiled_t)fp;
        // out viewed as 2D: 517120 rows x 128 floats, row stride 512 B
        cuuint64_t gdim[2]    = {128ull, (cuuint64_t)B_DIM * ROWS};
        cuuint64_t gstride[1] = {512ull};
        cuuint32_t box[2]     = {32u, (cuuint32_t)TS};
        cuuint32_t estr[2]    = {1u, 1u};
        CUresult r = encode(&tmap, CU_TENSOR_MAP_DATA_TYPE_FLOAT32, 2, out,
                            gdim, gstride, box, estr,
                            CU_TENSOR_MAP_INTERLEAVE_NONE,
                            CU_TENSOR_MAP_SWIZZLE_NONE,
                            CU_TENSOR_MAP_L2_PROMOTION_L2_128B,
                            CU_TENSOR_MAP_FLOAT_OOB_FILL_NONE);
        if (r == CUDA_SUCCESS) use_tma = 1;
    }

    dim3 grid(L_DIM / TS, D_DIM / (DT * 4), B_DIM);   // 16 x 4 x 128 = 8192 CTAs
    msse_kernel<<<grid, NTHREADS, SMEM_BYTES>>>(x, mask, out, tmap, use_tma);
}

// round 12
// speedup vs baseline: 1.3282x; 1.3282x over previous
#include <cuda_runtime.h>
#include <cuda_bf16.h>

// Problem constants
#define B_DIM 128
#define L_DIM 1024
#define D_DIM 128
#define DVF   32          // D/4 float4 groups (full row)
#define DT    8           // float4 groups per D-tile
#define TS    64          // starts per chunk
#define NPOS  96          // TS + 31 halo (padded to 96)
#define NS4   92          // TS + 28 sliding-4-sum rows
#define NTH   256
#define GRID  1184        // 148 SMs x 8 CTAs: one persistent wave
#define NCH   8192        // 16 L-chunks x 4 D-tiles x 128 batches

// Output row offsets for window sizes 4, 8, 16, 32
#define OFF4  0
#define OFF8  1021
#define OFF16 2038
#define OFF32 3047
#define ROWS  4040

// Shared memory: double-buffered s4 / inv / msk
#define S4SZ  (NS4 * DT)                 // float4 per buffer
#define SMEM_FLOATS (2 * S4SZ * 4 + 2 * 4 * TS + 2 * NPOS)
#define SMEM_BYTES  (SMEM_FLOATS * 4)

__device__ __forceinline__ float4 add4(float4 a, float4 b) {
    return make_float4(a.x + b.x, a.y + b.y, a.z + b.z, a.w + b.w);
}
__device__ __forceinline__ float4 scl4(float4 a, float s) {
    return make_float4(a.x * s, a.y * s, a.z * s, a.w * s);
}
__device__ __forceinline__ void decode(int t, int& b, int& dbase, int& s0) {
    b     = t & 127;
    dbase = ((t >> 7) & 3) * DT;
    s0    = (t >> 9) * TS;
}

extern __shared__ float smem_raw[];

__global__ __launch_bounds__(NTH, 8)
void msse_kernel(const float* __restrict__ x,
                 const int* __restrict__ mask,
                 float* __restrict__ out)
{
    const int tid = threadIdx.x;
    const int t0  = blockIdx.x;

    float4* s4buf  = reinterpret_cast<float4*>(smem_raw);           // [2][S4SZ]
    float*  invbuf = reinterpret_cast<float*>(s4buf + 2 * S4SZ);    // [2][4*TS]
    int*    mskbuf = reinterpret_cast<int*>(invbuf + 2 * 4 * TS);   // [2][NPOS]

    // ---- prologue: mask for first chunk into slot 0 ----
    {
        int b, dbase, s0;
        decode(t0, b, dbase, s0);
        if (tid < NPOS) {
            int g = s0 + tid;
            mskbuf[tid] = (g < L_DIM) ? mask[(size_t)b * L_DIM + g] : 0;
        }
    }
    __syncthreads();

    int prev_t = -1;
    int s = 0;

    for (int t = t0; t < NCH; t += GRID) {
        // ========== drain: outputs for prev chunk (slot s^1) =============
        if (prev_t >= 0) {
            int b, dbase, s0;
            decode(prev_t, b, dbase, s0);
            const float4* s4  = s4buf + (s ^ 1) * S4SZ;
            const float*  inv = invbuf + (s ^ 1) * 4 * TS;
            float4* outb = reinterpret_cast<float4*>(out + (size_t)b * ROWS * D_DIM);

            const int q   = tid & 7;
            const int idx = tid >> 3;       // 0..31
            const int jm  = idx & 3;
            const int kk  = idx >> 2;       // 0..7
            const int j0  = jm + 8 * kk;    // first start of pair
            const int j1  = j0 + 4;
            const int gi0 = s0 + j0;
            const int gi1 = s0 + j1;
            const int oq  = dbase + q;
            const float4* sp = s4 + j0 * DT + q;

            float4 a    = sp[0];
            float4 accA = a;
            if (gi0 <= L_DIM - 4)
                __stcs(&outb[(OFF4 + gi0) * DVF + oq], scl4(a, inv[0 * TS + j0]));
            a = sp[4 * DT];
            float4 accB = a;
            if (gi1 <= L_DIM - 4)
                __stcs(&outb[(OFF4 + gi1) * DVF + oq], scl4(a, inv[0 * TS + j1]));
            accA = add4(accA, a);
            if (gi0 <= L_DIM - 8)
                __stcs(&outb[(OFF8 + gi0) * DVF + oq], scl4(accA, inv[1 * TS + j0]));
            a = sp[8 * DT];
            accB = add4(accB, a);
            if (gi1 <= L_DIM - 8)
                __stcs(&outb[(OFF8 + gi1) * DVF + oq], scl4(accB, inv[1 * TS + j1]));
            accA = add4(accA, a);
            a = sp[12 * DT];
            accA = add4(accA, a);
            if (gi0 <= L_DIM - 16)
                __stcs(&outb[(OFF16 + gi0) * DVF + oq], scl4(accA, inv[2 * TS + j0]));
            accB = add4(accB, a);
            a = sp[16 * DT];
            accB = add4(accB, a);
            if (gi1 <= L_DIM - 16)
                __stcs(&outb[(OFF16 + gi1) * DVF + oq], scl4(accB, inv[2 * TS + j1]));
            accA = add4(accA, a);
            a = sp[20 * DT];
            accA = add4(accA, a);
            accB = add4(accB, a);
            a = sp[24 * DT];
            accA = add4(accA, a);
            accB = add4(accB, a);
            a = sp[28 * DT];
            accA = add4(accA, a);
            if (gi0 <= L_DIM - 32)
                __stcs(&outb[(OFF32 + gi0) * DVF + oq], scl4(accA, inv[3 * TS + j0]));
            accB = add4(accB, a);
            a = sp[32 * DT];
            accB = add4(accB, a);
            if (gi1 <= L_DIM - 32)
                __stcs(&outb[(OFF32 + gi1) * DVF + oq], scl4(accB, inv[3 * TS + j1]));
        }

        // ========== build: s4 + inv for chunk t (slot s) ==================
        {
            int b, dbase, s0;
            decode(t, b, dbase, s0);
            const int* msk = mskbuf + s * NPOS;
            float4*    s4  = s4buf + s * S4SZ;
            float*     inv = invbuf + s * 4 * TS;

            const float4* xrow = reinterpret_cast<const float4*>(
                x + (size_t)b * L_DIM * D_DIM);
            const float4 fz = make_float4(0.f, 0.f, 0.f, 0.f);

            for (int i = tid; i < NS4 * DT; i += NTH) {
                int p = i >> 3;
                int q = i & 7;
                const float4* base = xrow + (size_t)(s0 + p) * DVF + dbase + q;
                float4 acc = fz;
                #pragma unroll
                for (int k = 0; k < 4; k++) {
                    if (msk[p + k]) acc = add4(acc, __ldg(base + k * DVF));
                }
                s4[i] = acc;
            }

            if (tid < TS) {
                int j = tid;
                int c = 0;
                #pragma unroll
                for (int k = 0; k < 4; k++)  c += msk[j + k];
                int c4 = c;
                #pragma unroll
                for (int k = 4; k < 8; k++)  c += msk[j + k];
                int c8 = c;
                #pragma unroll
                for (int k = 8; k < 16; k++) c += msk[j + k];
                int c16 = c;
                #pragma unroll
                for (int k = 16; k < 32; k++) c += msk[j + k];
                int c32 = c;
                inv[0 * TS + j] = 1.0f / (float)(c4  > 1 ? c4  : 1);
                inv[1 * TS + j] = 1.0f / (float)(c8  > 1 ? c8  : 1);
                inv[2 * TS + j] = 1.0f / (float)(c16 > 1 ? c16 : 1);
                inv[3 * TS + j] = 1.0f / (float)(c32 > 1 ? c32 : 1);
            }
        }

        // ========== prefetch: mask for chunk t+GRID into slot s^1 =========
        if (t + GRID < NCH && tid < NPOS) {
            int b, dbase, s0;
            decode(t + GRID, b, dbase, s0);
            int g = s0 + tid;
            mskbuf[(s ^ 1) * NPOS + tid] =
                (g < L_DIM) ? mask[(size_t)b * L_DIM + g] : 0;
        }

        __syncthreads();
        prev_t = t;
        s ^= 1;
    }

    // ========== epilogue: drain last chunk (slot s^1) =====================
    if (prev_t >= 0) {
        int b, dbase, s0;
        decode(prev_t, b, dbase, s0);
        const float4* s4  = s4buf + (s ^ 1) * S4SZ;
        const float*  inv = invbuf + (s ^ 1) * 4 * TS;
        float4* outb = reinterpret_cast<float4*>(out + (size_t)b * ROWS * D_DIM);

        const int q   = tid & 7;
        const int idx = tid >> 3;
        const int jm  = idx & 3;
        const int kk  = idx >> 2;
        const int j0  = jm + 8 * kk;
        const int j1  = j0 + 4;
        const int gi0 = s0 + j0;
        const int gi1 = s0 + j1;
        const int oq  = dbase + q;
        const float4* sp = s4 + j0 * DT + q;

        float4 a    = sp[0];
        float4 accA = a;
        if (gi0 <= L_DIM - 4)
            __stcs(&outb[(OFF4 + gi0) * DVF + oq], scl4(a, inv[0 * TS + j0]));
        a = sp[4 * DT];
        float4 accB = a;
        if (gi1 <= L_DIM - 4)
            __stcs(&outb[(OFF4 + gi1) * DVF + oq], scl4(a, inv[0 * TS + j1]));
        accA = add4(accA, a);
        if (gi0 <= L_DIM - 8)
            __stcs(&outb[(OFF8 + gi0) * DVF + oq], scl4(accA, inv[1 * TS + j0]));
        a = sp[8 * DT];
        accB = add4(accB, a);
        if (gi1 <= L_DIM - 8)
            __stcs(&outb[(OFF8 + gi1) * DVF + oq], scl4(accB, inv[1 * TS + j1]));
        accA = add4(accA, a);
        a = sp[12 * DT];
        accA = add4(accA, a);
        if (gi0 <= L_DIM - 16)
            __stcs(&outb[(OFF16 + gi0) * DVF + oq], scl4(accA, inv[2 * TS + j0]));
        accB = add4(accB, a);
        a = sp[16 * DT];
        accB = add4(accB, a);
        if (gi1 <= L_DIM - 16)
            __stcs(&outb[(OFF16 + gi1) * DVF + oq], scl4(accB, inv[2 * TS + j1]));
        accA = add4(accA, a);
        a = sp[20 * DT];
        accA = add4(accA, a);
        accB = add4(accB, a);
        a = sp[24 * DT];
        accA = add4(accA, a);
        accB = add4(accB, a);
        a = sp[28 * DT];
        accA = add4(accA, a);
        if (gi0 <= L_DIM - 32)
            __stcs(&outb[(OFF32 + gi0) * DVF + oq], scl4(accA, inv[3 * TS + j0]));
        accB = add4(accB, a);
        a = sp[32 * DT];
        accB = add4(accB, a);
        if (gi1 <= L_DIM - 32)
            __stcs(&outb[(OFF32 + gi1) * DVF + oq], scl4(accB, inv[3 * TS + j1]));
    }
}

extern "C" void kernel_launch(void* const* d_in, const int* in_sizes, int n_in,
                              void* d_out, int out_size)
{
    const float* x    = (const float*)d_in[0];
    const int*   mask = (const int*)d_in[1];
    float*       out  = (float*)d_out;

    cudaFuncSetAttribute(msse_kernel,
                         cudaFuncAttributeMaxDynamicSharedMemorySize, SMEM_BYTES);

    msse_kernel<<<GRID, NTH, SMEM_BYTES>>>(x, mask, out);
}

// round 13
// speedup vs baseline: 1.3329x; 1.0036x over previous
#include <cuda_runtime.h>
#include <cuda_bf16.h>

// Problem constants
#define B_DIM 128
#define L_DIM 1024
#define D_DIM 128
#define DVF   32          // D/4 float4 groups (full row)
#define DT    8           // float4 groups per D-tile
#define TS    64          // starts per chunk
#define NPOS  96          // TS + 31 halo (padded to 96)
#define NS4   92          // TS + 28 sliding-4-sum rows
#define NTH   256
#define GRID  1184        // 148 SMs x 8 CTAs: one persistent wave
#define NCH   8192        // 16 L-chunks x 4 D-tiles x 128 batches

// Output row offsets for window sizes 4, 8, 16, 32
#define OFF4  0
#define OFF8  1021
#define OFF16 2038
#define OFF32 3047
#define ROWS  4040

// Shared memory: double-buffered s4 / inv / msk
#define S4SZ  (NS4 * DT)                 // float4 per buffer
#define SMEM_FLOATS (2 * S4SZ * 4 + 2 * 4 * TS + 2 * NPOS)
#define SMEM_BYTES  (SMEM_FLOATS * 4)

__device__ __forceinline__ float4 add4(float4 a, float4 b) {
    return make_float4(a.x + b.x, a.y + b.y, a.z + b.z, a.w + b.w);
}
__device__ __forceinline__ float4 scl4(float4 a, float s) {
    return make_float4(a.x * s, a.y * s, a.z * s, a.w * s);
}
__device__ __forceinline__ void decode(int t, int& b, int& dbase, int& s0) {
    b     = t & 127;
    dbase = ((t >> 7) & 3) * DT;
    s0    = (t >> 9) * TS;
}

extern __shared__ float smem_raw[];

__global__ __launch_bounds__(NTH, 8)
void msse_kernel(const float* __restrict__ x,
                 const int* __restrict__ mask,
                 float* __restrict__ out)
{
    const int tid = threadIdx.x;
    const int t0  = blockIdx.x;

    float4* s4buf  = reinterpret_cast<float4*>(smem_raw);           // [2][S4SZ]
    float*  invbuf = reinterpret_cast<float*>(s4buf + 2 * S4SZ);    // [2][4*TS]
    int*    mskbuf = reinterpret_cast<int*>(invbuf + 2 * 4 * TS);   // [2][NPOS]

    // ---- prologue: mask for first chunk into slot 0 ----
    {
        int b, dbase, s0;
        decode(t0, b, dbase, s0);
        if (tid < NPOS) {
            int g = s0 + tid;
            mskbuf[tid] = (g < L_DIM) ? mask[(size_t)b * L_DIM + g] : 0;
        }
    }
    __syncthreads();

    int prev_t = -1;
    int s = 0;

    for (int t = t0; t < NCH; t += GRID) {
        // ========== drain: outputs for prev chunk (slot s^1) =============
        if (prev_t >= 0) {
            int b, dbase, s0;
            decode(prev_t, b, dbase, s0);
            const float4* s4  = s4buf + (s ^ 1) * S4SZ;
            const float*  inv = invbuf + (s ^ 1) * 4 * TS;
            float4* outb = reinterpret_cast<float4*>(out + (size_t)b * ROWS * D_DIM);

            const int q   = tid & 7;
            const int idx = tid >> 3;       // 0..31
            const int jm  = idx & 3;
            const int kk  = idx >> 2;       // 0..7
            const int j0  = jm + 8 * kk;    // first start of pair
            const int j1  = j0 + 4;
            const int gi0 = s0 + j0;
            const int gi1 = s0 + j1;
            const int oq  = dbase + q;
            const float4* sp = s4 + j0 * DT + q;

            float4 a    = sp[0];
            float4 accA = a;
            if (gi0 <= L_DIM - 4)
                __stcs(&outb[(OFF4 + gi0) * DVF + oq], scl4(a, inv[0 * TS + j0]));
            a = sp[4 * DT];
            float4 accB = a;
            if (gi1 <= L_DIM - 4)
                __stcs(&outb[(OFF4 + gi1) * DVF + oq], scl4(a, inv[0 * TS + j1]));
            accA = add4(accA, a);
            if (gi0 <= L_DIM - 8)
                __stcs(&outb[(OFF8 + gi0) * DVF + oq], scl4(accA, inv[1 * TS + j0]));
            a = sp[8 * DT];
            accB = add4(accB, a);
            if (gi1 <= L_DIM - 8)
                __stcs(&outb[(OFF8 + gi1) * DVF + oq], scl4(accB, inv[1 * TS + j1]));
            accA = add4(accA, a);
            a = sp[12 * DT];
            accA = add4(accA, a);
            if (gi0 <= L_DIM - 16)
                __stcs(&outb[(OFF16 + gi0) * DVF + oq], scl4(accA, inv[2 * TS + j0]));
            accB = add4(accB, a);
            a = sp[16 * DT];
            accB = add4(accB, a);
            if (gi1 <= L_DIM - 16)
                __stcs(&outb[(OFF16 + gi1) * DVF + oq], scl4(accB, inv[2 * TS + j1]));
            accA = add4(accA, a);
            a = sp[20 * DT];
            accA = add4(accA, a);
            accB = add4(accB, a);
            a = sp[24 * DT];
            accA = add4(accA, a);
            accB = add4(accB, a);
            a = sp[28 * DT];
            accA = add4(accA, a);
            if (gi0 <= L_DIM - 32)
                __stcs(&outb[(OFF32 + gi0) * DVF + oq], scl4(accA, inv[3 * TS + j0]));
            accB = add4(accB, a);
            a = sp[32 * DT];
            accB = add4(accB, a);
            if (gi1 <= L_DIM - 32)
                __stcs(&outb[(OFF32 + gi1) * DVF + oq], scl4(accB, inv[3 * TS + j1]));
        }

        // ========== build: s4 (threads 0-183, rolling) + inv (192-255) ====
        {
            int b, dbase, s0;
            decode(t, b, dbase, s0);
            const int* msk = mskbuf + s * NPOS;
            float4*    s4  = s4buf + s * S4SZ;
            float*     inv = invbuf + s * 4 * TS;

            if (tid < 184) {
                // run r covers s4 rows [4r, 4r+4); needs x rows [4r, 4r+7)
                const int r  = tid >> 3;      // 0..22
                const int q  = tid & 7;
                const int p0 = r * 4;
                const float4* xrow = reinterpret_cast<const float4*>(
                    x + (size_t)b * L_DIM * D_DIM);
                const float4* base = xrow + (size_t)(s0 + p0) * DVF + dbase + q;
                const float4 fz = make_float4(0.f, 0.f, 0.f, 0.f);

                float4 w0 = msk[p0]     ? __ldg(base)           : fz;
                float4 w1 = msk[p0 + 1] ? __ldg(base + DVF)     : fz;
                float4 w2 = msk[p0 + 2] ? __ldg(base + 2 * DVF) : fz;
                #pragma unroll
                for (int i = 0; i < 4; i++) {
                    float4 w3 = msk[p0 + i + 3] ? __ldg(base + (i + 3) * DVF) : fz;
                    s4[(p0 + i) * DT + q] = add4(add4(w0, w1), add4(w2, w3));
                    w0 = w1; w1 = w2; w2 = w3;
                }
            } else if (tid >= 192) {
                const int j = tid - 192;      // 0..63
                int c = 0;
                #pragma unroll
                for (int k = 0; k < 4; k++)  c += msk[j + k];
                int c4 = c;
                #pragma unroll
                for (int k = 4; k < 8; k++)  c += msk[j + k];
                int c8 = c;
                #pragma unroll
                for (int k = 8; k < 16; k++) c += msk[j + k];
                int c16 = c;
                #pragma unroll
                for (int k = 16; k < 32; k++) c += msk[j + k];
                int c32 = c;
                inv[0 * TS + j] = 1.0f / (float)(c4  > 1 ? c4  : 1);
                inv[1 * TS + j] = 1.0f / (float)(c8  > 1 ? c8  : 1);
                inv[2 * TS + j] = 1.0f / (float)(c16 > 1 ? c16 : 1);
                inv[3 * TS + j] = 1.0f / (float)(c32 > 1 ? c32 : 1);
            }
        }

        // ========== prefetch: mask for chunk t+GRID into slot s^1 =========
        if (t + GRID < NCH && tid < NPOS) {
            int b, dbase, s0;
            decode(t + GRID, b, dbase, s0);
            int g = s0 + tid;
            mskbuf[(s ^ 1) * NPOS + tid] =
                (g < L_DIM) ? mask[(size_t)b * L_DIM + g] : 0;
        }

        __syncthreads();
        prev_t = t;
        s ^= 1;
    }

    // ========== epilogue: drain last chunk (slot s^1) =====================
    if (prev_t >= 0) {
        int b, dbase, s0;
        decode(prev_t, b, dbase, s0);
        const float4* s4  = s4buf + (s ^ 1) * S4SZ;
        const float*  inv = invbuf + (s ^ 1) * 4 * TS;
        float4* outb = reinterpret_cast<float4*>(out + (size_t)b * ROWS * D_DIM);

        const int q   = tid & 7;
        const int idx = tid >> 3;
        const int jm  = idx & 3;
        const int kk  = idx >> 2;
        const int j0  = jm + 8 * kk;
        const int j1  = j0 + 4;
        const int gi0 = s0 + j0;
        const int gi1 = s0 + j1;
        const int oq  = dbase + q;
        const float4* sp = s4 + j0 * DT + q;

        float4 a    = sp[0];
        float4 accA = a;
        if (gi0 <= L_DIM - 4)
            __stcs(&outb[(OFF4 + gi0) * DVF + oq], scl4(a, inv[0 * TS + j0]));
        a = sp[4 * DT];
        float4 accB = a;
        if (gi1 <= L_DIM - 4)
            __stcs(&outb[(OFF4 + gi1) * DVF + oq], scl4(a, inv[0 * TS + j1]));
        accA = add4(accA, a);
        if (gi0 <= L_DIM - 8)
            __stcs(&outb[(OFF8 + gi0) * DVF + oq], scl4(accA, inv[1 * TS + j0]));
        a = sp[8 * DT];
        accB = add4(accB, a);
        if (gi1 <= L_DIM - 8)
            __stcs(&outb[(OFF8 + gi1) * DVF + oq], scl4(accB, inv[1 * TS + j1]));
        accA = add4(accA, a);
        a = sp[12 * DT];
        accA = add4(accA, a);
        if (gi0 <= L_DIM - 16)
            __stcs(&outb[(OFF16 + gi0) * DVF + oq], scl4(accA, inv[2 * TS + j0]));
        accB = add4(accB, a);
        a = sp[16 * DT];
        accB = add4(accB, a);
        if (gi1 <= L_DIM - 16)
            __stcs(&outb[(OFF16 + gi1) * DVF + oq], scl4(accB, inv[2 * TS + j1]));
        accA = add4(accA, a);
        a = sp[20 * DT];
        accA = add4(accA, a);
        accB = add4(accB, a);
        a = sp[24 * DT];
        accA = add4(accA, a);
        accB = add4(accB, a);
        a = sp[28 * DT];
        accA = add4(accA, a);
        if (gi0 <= L_DIM - 32)
            __stcs(&outb[(OFF32 + gi0) * DVF + oq], scl4(accA, inv[3 * TS + j0]));
        accB = add4(accB, a);
        a = sp[32 * DT];
        accB = add4(accB, a);
        if (gi1 <= L_DIM - 32)
            __stcs(&outb[(OFF32 + gi1) * DVF + oq], scl4(accB, inv[3 * TS + j1]));
    }
}

extern "C" void kernel_launch(void* const* d_in, const int* in_sizes, int n_in,
                              void* d_out, int out_size)
{
    const float* x    = (const float*)d_in[0];
    const int*   mask = (const int*)d_in[1];
    float*       out  = (float*)d_out;

    cudaFuncSetAttribute(msse_kernel,
                         cudaFuncAttributeMaxDynamicSharedMemorySize, SMEM_BYTES);

    msse_kernel<<<GRID, NTH, SMEM_BYTES>>>(x, mask, out);
}